// round 3
// baseline (speedup 1.0000x reference)
#include <cuda_runtime.h>
#include <math.h>

// Problem constants
#define NV 16384   // encoded vectors
#define DD 256     // embedding dim
#define KC 4096    // codebook size

// Main GEMM-argmin tiling
#define BM 128     // rows per block
#define BN 64      // codes per tile
#define ZS_STRIDE 132  // BM + 4 pad (keeps 16B alignment, kills transpose-store conflicts)
#define CS_STRIDE 68   // BN + 4 pad
#define SMEM_BYTES ((DD * ZS_STRIDE + DD * CS_STRIDE) * 4)  // 204800 B

// Scratch (no allocations allowed)
__device__ float g_cbnorm[KC];
__device__ int   g_indices[NV];
__device__ int   g_counts[KC];
__device__ float g_partials[512];

// ---------------------------------------------------------------------------
// Kernel 1: codebook row norms (one warp per code) + zero counts
// ---------------------------------------------------------------------------
__global__ void prep_kernel(const float* __restrict__ cb) {
    int gid  = blockIdx.x * 256 + threadIdx.x;   // grid 512 x 256 = 4096 warps
    int code = gid >> 5;
    int lane = gid & 31;
    const float* row = cb + (size_t)code * DD;
    float s = 0.f;
#pragma unroll
    for (int i = 0; i < DD; i += 32) {
        float v = row[i + lane];
        s += v * v;
    }
#pragma unroll
    for (int off = 16; off; off >>= 1)
        s += __shfl_down_sync(0xffffffffu, s, off);
    if (lane == 0) g_cbnorm[code] = s;
    if (gid < KC) g_counts[gid] = 0;
}

// ---------------------------------------------------------------------------
// Kernel 2: fused distance GEMM + per-row argmin
//   dist(n,k) = ||cb_k||^2 - 2 * dot(ze_n, cb_k)   (per-row ||ze||^2 omitted:
//   constant per row, does not change argmin)
//   Block: 128 rows x all 4096 codes, 64-code tiles, full D resident in smem.
//   256 threads as 16(tx: codes) x 16(ty: rows); TM=8, TN=4.
// ---------------------------------------------------------------------------
__global__ void __launch_bounds__(256, 1) argmin_kernel(
    const float* __restrict__ ze, const float* __restrict__ cb,
    float* __restrict__ out_idx)
{
    extern __shared__ float sm[];
    float* zs = sm;                    // [DD][ZS_STRIDE]  transposed ze tile
    float* cs = sm + DD * ZS_STRIDE;   // [DD][CS_STRIDE]  transposed cb tile

    const int tid = threadIdx.x;
    const int tx  = tid & 15;          // code group
    const int ty  = tid >> 4;          // row group
    const int r0  = blockIdx.x * BM;

    // Load ze tile transposed: zs[d][row]. Warp lanes -> consecutive rows at
    // same d4, so smem scalar stores are stride-1 (conflict-free).
    for (int f = tid; f < BM * (DD / 4); f += 256) {
        int row = f & (BM - 1);
        int d4  = f >> 7;   // BM == 128
        float4 v = *(const float4*)(ze + (size_t)(r0 + row) * DD + d4 * 4);
        zs[(4 * d4 + 0) * ZS_STRIDE + row] = v.x;
        zs[(4 * d4 + 1) * ZS_STRIDE + row] = v.y;
        zs[(4 * d4 + 2) * ZS_STRIDE + row] = v.z;
        zs[(4 * d4 + 3) * ZS_STRIDE + row] = v.w;
    }

    float best[8];
    int   bidx[8];
#pragma unroll
    for (int i = 0; i < 8; i++) { best[i] = 3.4e38f; bidx[i] = 0; }

    const float* zp = zs + ty * 8;
    const float* cp = cs + tx * 4;

    for (int t0 = 0; t0 < KC; t0 += BN) {
        __syncthreads();   // prior compute done (and, first iter, ze stores done)
        for (int f = tid; f < BN * (DD / 4); f += 256) {
            int code = f & (BN - 1);
            int d4   = f >> 6;   // BN == 64
            float4 v = *(const float4*)(cb + (size_t)(t0 + code) * DD + d4 * 4);
            cs[(4 * d4 + 0) * CS_STRIDE + code] = v.x;
            cs[(4 * d4 + 1) * CS_STRIDE + code] = v.y;
            cs[(4 * d4 + 2) * CS_STRIDE + code] = v.z;
            cs[(4 * d4 + 3) * CS_STRIDE + code] = v.w;
        }
        __syncthreads();

        float acc[8][4];
#pragma unroll
        for (int i = 0; i < 8; i++)
#pragma unroll
            for (int j = 0; j < 4; j++) acc[i][j] = 0.f;

#pragma unroll 8
        for (int d = 0; d < DD; d++) {
            float4 a0 = *(const float4*)(zp + d * ZS_STRIDE);
            float4 a1 = *(const float4*)(zp + d * ZS_STRIDE + 4);
            float4 b  = *(const float4*)(cp + d * CS_STRIDE);
            float av[8] = {a0.x, a0.y, a0.z, a0.w, a1.x, a1.y, a1.z, a1.w};
            float bv[4] = {b.x, b.y, b.z, b.w};
#pragma unroll
            for (int i = 0; i < 8; i++)
#pragma unroll
                for (int j = 0; j < 4; j++)
                    acc[i][j] = fmaf(av[i], bv[j], acc[i][j]);
        }

        // Running-min update for this thread's 4 codes
        float cn[4];
#pragma unroll
        for (int j = 0; j < 4; j++) cn[j] = __ldg(g_cbnorm + t0 + tx * 4 + j);
#pragma unroll
        for (int i = 0; i < 8; i++) {
#pragma unroll
            for (int j = 0; j < 4; j++) {
                float dv = cn[j] - 2.f * acc[i][j];
                if (dv < best[i]) { best[i] = dv; bidx[i] = t0 + tx * 4 + j; }
            }
        }
    }

    // Reduce across the 16 tx threads sharing the same rows (half-warp groups)
#pragma unroll
    for (int i = 0; i < 8; i++) {
        float v = best[i];
        int   ix = bidx[i];
#pragma unroll
        for (int off = 8; off; off >>= 1) {
            float ov = __shfl_down_sync(0xffffffffu, v, off, 16);
            int   oi = __shfl_down_sync(0xffffffffu, ix, off, 16);
            if (ov < v || (ov == v && oi < ix)) { v = ov; ix = oi; }
        }
        if (tx == 0) {
            int row = r0 + ty * 8 + i;
            g_indices[row] = ix;
            out_idx[row]   = (float)ix;
        }
    }
}

// ---------------------------------------------------------------------------
// Kernel 3: gather zq, accumulate squared-error partials, histogram counts
// ---------------------------------------------------------------------------
__global__ void gather_kernel(const float* __restrict__ ze,
                              const float* __restrict__ cb,
                              float* __restrict__ out_zq)
{
    __shared__ float red[256];
    int w    = threadIdx.x >> 5;
    int lane = threadIdx.x & 31;
    int r0   = blockIdx.x * 32;   // grid 512
    float s = 0.f;
#pragma unroll
    for (int rr = 0; rr < 4; rr++) {
        int row = r0 + rr * 8 + w;
        int idx = g_indices[row];
        if (lane == 0) atomicAdd(&g_counts[idx], 1);
        const float4* cpv = (const float4*)(cb + (size_t)idx * DD);
        const float4* zpv = (const float4*)(ze + (size_t)row * DD);
        float4*       opv = (float4*)(out_zq + (size_t)row * DD);
#pragma unroll
        for (int j = 0; j < 2; j++) {
            int e = lane + j * 32;   // 64 float4 per row
            float4 c = cpv[e];
            float4 z = zpv[e];
            opv[e] = c;
            float dx = c.x - z.x, dy = c.y - z.y, dz = c.z - z.z, dw = c.w - z.w;
            s += dx * dx + dy * dy + dz * dz + dw * dw;
        }
    }
    red[threadIdx.x] = s;
    __syncthreads();
    for (int off = 128; off; off >>= 1) {
        if (threadIdx.x < off) red[threadIdx.x] += red[threadIdx.x + off];
        __syncthreads();
    }
    if (threadIdx.x == 0) g_partials[blockIdx.x] = red[0];
}

// ---------------------------------------------------------------------------
// Kernel 4: losses + perplexity
// ---------------------------------------------------------------------------
__global__ void finalize_kernel(float* __restrict__ out)
{
    __shared__ float red[256];
    int t = threadIdx.x;

    // loss = mean((zq - ze)^2); e-loss and commit-loss are numerically equal
    float s = g_partials[t] + g_partials[t + 256];
    red[t] = s;
    __syncthreads();
    for (int off = 128; off; off >>= 1) {
        if (t < off) red[t] += red[t + off];
        __syncthreads();
    }
    if (t == 0) {
        float loss = red[0] / (float)((size_t)NV * DD);
        out[(size_t)NV + (size_t)NV * DD + 0] = loss;
        out[(size_t)NV + (size_t)NV * DD + 1] = loss;
    }
    __syncthreads();

    // perplexity = exp(-sum(p*log(p+1e-10))), p = counts/10 (faithful /10 ->
    // sum ~ -1.4e3 -> expf overflows to +inf, same as the fp32 reference)
    float e = 0.f;
    for (int k = t; k < KC; k += 256) {
        float p = (float)g_counts[k] * 0.1f;
        e += p * logf(p + 1e-10f);
    }
    red[t] = e;
    __syncthreads();
    for (int off = 128; off; off >>= 1) {
        if (t < off) red[t] += red[t + off];
        __syncthreads();
    }
    if (t == 0) out[(size_t)NV + (size_t)NV * DD + 2] = expf(-red[0]);
}

// ---------------------------------------------------------------------------
extern "C" void kernel_launch(void* const* d_in, const int* in_sizes, int n_in,
                              void* d_out, int out_size)
{
    const float* ze = (const float*)d_in[0];
    const float* cb = (const float*)d_in[1];
    float* out = (float*)d_out;

    cudaFuncSetAttribute(argmin_kernel,
                         cudaFuncAttributeMaxDynamicSharedMemorySize, SMEM_BYTES);

    prep_kernel<<<512, 256>>>(cb);
    argmin_kernel<<<NV / BM, 256, SMEM_BYTES>>>(ze, cb, out);
    gather_kernel<<<512, 256>>>(ze, cb, out + NV);
    finalize_kernel<<<1, 256>>>(out);
}

// round 5
// speedup vs baseline: 1.7072x; 1.7072x over previous
#include <cuda_runtime.h>
#include <cuda_fp16.h>
#include <math.h>
#include <stdint.h>

// ---------------------------------------------------------------------------
// Problem constants
// ---------------------------------------------------------------------------
#define NV 16384   // encoded vectors
#define DD 256     // embedding dim
#define KC 4096    // codebook size

// GEMM tiling (Ampere-style mma.sync, works on plain sm_103 target)
#define BM 128
#define BN 128
#define BK 32                         // fp16 elems per K chunk
#define DKS (DD / BK)                 // 8
#define NTILES (KC / BN)              // 32
#define TOTAL_CHUNKS (NTILES * DKS)   // 256

#define RS 40                         // padded row stride in halves (80 B = 5*16B -> conflict-free ldmatrix)
#define TILE_B (128 * RS * 2)         // 10240 B per operand tile
#define STAGE_B (4 * TILE_B)          // Ah, Al, Bh, Bl = 40960 B
#define SMEM_REQ (2 * STAGE_B)        // 81920 B (double buffered)

// ---------------------------------------------------------------------------
// Scratch (no allocations allowed)
// ---------------------------------------------------------------------------
__device__ __half g_zehi16[NV * DD];
__device__ __half g_zelo16[NV * DD];
__device__ __half g_cbhi16[KC * DD];
__device__ __half g_cblo16[KC * DD];
__device__ float  g_cn2[KC];          // 0.5 * ||cb_k||^2
__device__ int    g_counts[KC];
__device__ float  g_partials[128];

// ---------------------------------------------------------------------------
// PTX helpers (all plain-sm_80+ features)
// ---------------------------------------------------------------------------
__device__ __forceinline__ uint32_t smem_u32(const void* p) {
    uint32_t a;
    asm("{ .reg .u64 t; cvta.to.shared.u64 t, %1; cvt.u32.u64 %0, t; }" : "=r"(a) : "l"(p));
    return a;
}
__device__ __forceinline__ void cp16(uint32_t dst, const void* src) {
    asm volatile("cp.async.cg.shared.global [%0], [%1], 16;" :: "r"(dst), "l"(src) : "memory");
}
#define CP_COMMIT() asm volatile("cp.async.commit_group;" ::: "memory")
#define CP_WAIT1()  asm volatile("cp.async.wait_group 1;" ::: "memory")
#define CP_WAIT0()  asm volatile("cp.async.wait_group 0;" ::: "memory")

#define LDMX4(r, addr) \
    asm volatile("ldmatrix.sync.aligned.m8n8.x4.shared.b16 {%0,%1,%2,%3}, [%4];" \
        : "=r"((r)[0]), "=r"((r)[1]), "=r"((r)[2]), "=r"((r)[3]) : "r"(addr))

#define MMA16816(d, a, b0v, b1v) \
    asm volatile("mma.sync.aligned.m16n8k16.row.col.f32.f16.f16.f32 " \
        "{%0,%1,%2,%3}, {%4,%5,%6,%7}, {%8,%9}, {%0,%1,%2,%3};" \
        : "+f"((d)[0]), "+f"((d)[1]), "+f"((d)[2]), "+f"((d)[3]) \
        : "r"((a)[0]), "r"((a)[1]), "r"((a)[2]), "r"((a)[3]), "r"(b0v), "r"(b1v))

// ---------------------------------------------------------------------------
// Kernel 1: fp16 hi/lo split of ze and codebook
// ---------------------------------------------------------------------------
__global__ void split_kernel(const float* __restrict__ ze, const float* __restrict__ cb) {
    int i = blockIdx.x * 256 + threadIdx.x;            // grid 5120 x 256 (exact)
    const float4* src; __half2 *dh, *dl; int j;
    if (i < NV * DD / 4) { src = (const float4*)ze; dh = (__half2*)g_zehi16; dl = (__half2*)g_zelo16; j = i; }
    else { src = (const float4*)cb; dh = (__half2*)g_cbhi16; dl = (__half2*)g_cblo16; j = i - NV * DD / 4; }
    float4 v = src[j];
    __half hx = __float2half_rn(v.x), hy = __float2half_rn(v.y);
    __half hz = __float2half_rn(v.z), hw = __float2half_rn(v.w);
    __half lx = __float2half_rn(v.x - __half2float(hx));
    __half ly = __float2half_rn(v.y - __half2float(hy));
    __half lz = __float2half_rn(v.z - __half2float(hz));
    __half lw = __float2half_rn(v.w - __half2float(hw));
    dh[2 * j]     = __halves2half2(hx, hy);
    dh[2 * j + 1] = __halves2half2(hz, hw);
    dl[2 * j]     = __halves2half2(lx, ly);
    dl[2 * j + 1] = __halves2half2(lz, lw);
}

// ---------------------------------------------------------------------------
// Kernel 2: codebook half-norms (warp per code) + zero counts
// ---------------------------------------------------------------------------
__global__ void norm_kernel(const float* __restrict__ cb) {
    int gid  = blockIdx.x * 256 + threadIdx.x;   // 512 x 256 = 4096 warps
    int code = gid >> 5;
    int lane = gid & 31;
    const float* row = cb + (size_t)code * DD;
    float s = 0.f;
#pragma unroll
    for (int i = 0; i < DD; i += 32) { float v = row[i + lane]; s += v * v; }
#pragma unroll
    for (int off = 16; off; off >>= 1) s += __shfl_down_sync(0xffffffffu, s, off);
    if (lane == 0) g_cn2[code] = 0.5f * s;
    if (gid < KC) g_counts[gid] = 0;
}

// ---------------------------------------------------------------------------
// Kernel 3: 3xFP16 mma.sync GEMM + fused argmin + gather + loss partials
//   CTA: 128 rows x all 4096 codes (128-code tiles, full-D accumulate).
//   8 warps, warp grid 2(m) x 4(n), warp tile 64x32: 4 m16 x 4 n8 mma tiles.
//   D = Ahi*Bhi + Ahi*Blo + Alo*Bhi (fp32 accum).
//   score = dot - 0.5*||c||^2 maximized == distance argmin; first-min ties.
// ---------------------------------------------------------------------------
__global__ void __launch_bounds__(256, 1) argmin_kernel(
    const float* __restrict__ ze, const float* __restrict__ cb,
    float* __restrict__ out)
{
    extern __shared__ char smraw[];
    const uint32_t smb = smem_u32(smraw);

    const int tid    = threadIdx.x;
    const int lane   = tid & 31;
    const int wid    = tid >> 5;
    const int warp_m = wid & 1;       // 0..1 -> 64 rows each
    const int warp_n = wid >> 1;      // 0..3 -> 32 cols each
    const int r0     = blockIdx.x * BM;

    // ---- per-thread ldmatrix source offsets (within an operand tile) ----
    // A (x4 over one m16 tile): lanes 0-15 -> rows +lane, col kk;
    //                           lanes16-31 -> rows +(lane-16), col kk+8
    const int a_row  = warp_m * 64 + (lane & 15);
    const int a_cofs = (lane >> 4) << 3;
    // B (x4 over two n8 tiles): row = +((lane>>4)<<3) + (lane&7), col kk + (((lane>>3)&1)<<3)
    const int b_row  = warp_n * 32 + ((lane >> 4) << 3) + (lane & 7);
    const int b_cofs = ((lane >> 3) & 1) << 3;

    const uint32_t a_off = (uint32_t)(a_row * RS + a_cofs) * 2;
    const uint32_t b_off = (uint32_t)(b_row * RS + b_cofs) * 2;

    // ---- global load mapping: 4 tiles x 64 threads; 2 rows x 4 cp16 each ----
    const int lt    = tid & 63;
    const int ltile = tid >> 6;       // 0:Ah 1:Al 2:Bh 3:Bl

    float acc[16][4];
#pragma unroll
    for (int i = 0; i < 16; i++)
#pragma unroll
        for (int j = 0; j < 4; j++) acc[i][j] = 0.f;

    float best[8];
    int   bidx[8];
#pragma unroll
    for (int i = 0; i < 8; i++) { best[i] = -3.4e38f; bidx[i] = 0; }

    auto load_chunk = [&](int q) {
        const int nt = q >> 3, dk = q & 7;
        const uint32_t sb = smb + (q & 1) * STAGE_B + ltile * TILE_B;
        const __half* gbase;
        int grow0;
        if (ltile == 0)      { gbase = g_zehi16; grow0 = r0; }
        else if (ltile == 1) { gbase = g_zelo16; grow0 = r0; }
        else if (ltile == 2) { gbase = g_cbhi16; grow0 = nt * BN; }
        else                 { gbase = g_cblo16; grow0 = nt * BN; }
#pragma unroll
        for (int i = 0; i < 8; i++) {
            const int row = (lt << 1) + (i >> 2);
            const int c16 = i & 3;
            cp16(sb + (uint32_t)(row * RS + c16 * 8) * 2,
                 gbase + (size_t)(grow0 + row) * DD + dk * BK + c16 * 8);
        }
    };

    load_chunk(0); CP_COMMIT();

    for (int q = 0; q < TOTAL_CHUNKS; q++) {
        if (q + 1 < TOTAL_CHUNKS) { load_chunk(q + 1); CP_COMMIT(); CP_WAIT1(); }
        else                      { CP_WAIT0(); }
        __syncthreads();   // chunk q visible to all warps

        const uint32_t sb = smb + (q & 1) * STAGE_B;
        const uint32_t aH = sb,              aL = sb + TILE_B;
        const uint32_t bH = sb + 2 * TILE_B, bL = sb + 3 * TILE_B;

#pragma unroll
        for (int kk = 0; kk < BK; kk += 16) {
            uint32_t Ah[4][4], Al[4][4], Bh[2][4], Bl[2][4];
            const uint32_t ao = a_off + kk * 2;
            const uint32_t bo = b_off + kk * 2;
#pragma unroll
            for (int mt = 0; mt < 4; mt++) LDMX4(Ah[mt], aH + ao + mt * (16 * RS * 2));
#pragma unroll
            for (int p = 0; p < 2; p++)    LDMX4(Bh[p], bH + bo + p * (16 * RS * 2));
#pragma unroll
            for (int mt = 0; mt < 4; mt++)
#pragma unroll
                for (int nt = 0; nt < 4; nt++)
                    MMA16816(acc[mt * 4 + nt], Ah[mt], Bh[nt >> 1][(nt & 1) * 2], Bh[nt >> 1][(nt & 1) * 2 + 1]);
#pragma unroll
            for (int p = 0; p < 2; p++)    LDMX4(Bl[p], bL + bo + p * (16 * RS * 2));
#pragma unroll
            for (int mt = 0; mt < 4; mt++)
#pragma unroll
                for (int nt = 0; nt < 4; nt++)
                    MMA16816(acc[mt * 4 + nt], Ah[mt], Bl[nt >> 1][(nt & 1) * 2], Bl[nt >> 1][(nt & 1) * 2 + 1]);
#pragma unroll
            for (int mt = 0; mt < 4; mt++) LDMX4(Al[mt], aL + ao + mt * (16 * RS * 2));
#pragma unroll
            for (int mt = 0; mt < 4; mt++)
#pragma unroll
                for (int nt = 0; nt < 4; nt++)
                    MMA16816(acc[mt * 4 + nt], Al[mt], Bh[nt >> 1][(nt & 1) * 2], Bh[nt >> 1][(nt & 1) * 2 + 1]);
        }
        __syncthreads();   // all warps done with this stage before it is reloaded

        if ((q & 7) == 7) {
            // ---- end of code tile: fold in -0.5||c||^2, update running argmax ----
            const int ctile0 = (q >> 3) * BN + warp_n * 32;
            const int cbase  = ctile0 + (lane & 3) * 2;
#pragma unroll
            for (int j = 0; j < 4; j++) {
                const int   c0  = cbase + j * 8;
                const float cn0 = __ldg(g_cn2 + c0);
                const float cn1 = __ldg(g_cn2 + c0 + 1);
#pragma unroll
                for (int mt = 0; mt < 4; mt++) {
                    float* a = acc[mt * 4 + j];
                    const float v0 = a[0] - cn0, v1 = a[1] - cn1;   // row g
                    const float v2 = a[2] - cn0, v3 = a[3] - cn1;   // row g+8
                    const int rs0 = mt * 2, rs1 = mt * 2 + 1;
                    if (v0 > best[rs0]) { best[rs0] = v0; bidx[rs0] = c0; }
                    if (v1 > best[rs0]) { best[rs0] = v1; bidx[rs0] = c0 + 1; }
                    if (v2 > best[rs1]) { best[rs1] = v2; bidx[rs1] = c0; }
                    if (v3 > best[rs1]) { best[rs1] = v3; bidx[rs1] = c0 + 1; }
                    a[0] = a[1] = a[2] = a[3] = 0.f;
                }
            }
        }
    }

    // ---- cross-thread argmin reduction ----
    __syncthreads();   // stage smem free: reuse for reductions
    float* sBest = (float*)smraw;             // [128][4]
    int*   sIdx  = (int*)(smraw + 2048);      // [128][4]
    const int g = lane >> 2;
#pragma unroll
    for (int rs = 0; rs < 8; rs++) {
        float v = best[rs];
        int   ix = bidx[rs];
#pragma unroll
        for (int off = 1; off <= 2; off <<= 1) {
            float ov = __shfl_xor_sync(0xffffffffu, v, off);
            int   oi = __shfl_xor_sync(0xffffffffu, ix, off);
            if (ov > v || (ov == v && oi < ix)) { v = ov; ix = oi; }
        }
        if ((lane & 3) == 0) {
            const int rl = warp_m * 64 + (rs >> 1) * 16 + (rs & 1) * 8 + g;
            sBest[rl * 4 + warp_n] = v;
            sIdx[rl * 4 + warp_n]  = ix;
        }
    }
    __syncthreads();

    float s = 0.f;
    if (tid < 128) {
        float v = sBest[tid * 4];
        int   ix = sIdx[tid * 4];
#pragma unroll
        for (int w = 1; w < 4; w++) {
            const float ov = sBest[tid * 4 + w];
            const int   oi = sIdx[tid * 4 + w];
            if (ov > v || (ov == v && oi < ix)) { v = ov; ix = oi; }
        }
        const int row = r0 + tid;
        out[row] = (float)ix;
        atomicAdd(&g_counts[ix], 1);

        const float4* crow = (const float4*)(cb + (size_t)ix * DD);
        const float4* zrow = (const float4*)(ze + (size_t)row * DD);
        float4*       orow = (float4*)(out + NV + (size_t)row * DD);
#pragma unroll 4
        for (int j = 0; j < DD / 4; j++) {
            float4 c = crow[j], z = zrow[j];
            orow[j] = c;
            float dx = c.x - z.x, dy = c.y - z.y, dz = c.z - z.z, dw = c.w - z.w;
            s += dx * dx + dy * dy + dz * dz + dw * dw;
        }
    }
    __syncthreads();
    float* red = (float*)(smraw + 4096);
    red[tid] = s;
    __syncthreads();
    for (int off = 128; off; off >>= 1) {
        if (tid < off) red[tid] += red[tid + off];
        __syncthreads();
    }
    if (tid == 0) g_partials[blockIdx.x] = red[0];
}

// ---------------------------------------------------------------------------
// Kernel 4: losses + perplexity
// ---------------------------------------------------------------------------
__global__ void finalize_kernel(float* __restrict__ out) {
    __shared__ float red[256];
    const int t = threadIdx.x;

    red[t] = (t < 128) ? g_partials[t] : 0.f;
    __syncthreads();
    for (int off = 128; off; off >>= 1) {
        if (t < off) red[t] += red[t + off];
        __syncthreads();
    }
    if (t == 0) {
        float loss = red[0] / (float)((size_t)NV * DD);
        out[(size_t)NV + (size_t)NV * DD + 0] = loss;
        out[(size_t)NV + (size_t)NV * DD + 1] = loss;
    }
    __syncthreads();

    float e = 0.f;
    for (int k = t; k < KC; k += 256) {
        float p = (float)g_counts[k] * 0.1f;
        e += p * logf(p + 1e-10f);
    }
    red[t] = e;
    __syncthreads();
    for (int off = 128; off; off >>= 1) {
        if (t < off) red[t] += red[t + off];
        __syncthreads();
    }
    if (t == 0) out[(size_t)NV + (size_t)NV * DD + 2] = expf(-red[0]);
}

// ---------------------------------------------------------------------------
extern "C" void kernel_launch(void* const* d_in, const int* in_sizes, int n_in,
                              void* d_out, int out_size)
{
    const float* ze = (const float*)d_in[0];
    const float* cb = (const float*)d_in[1];
    float* out = (float*)d_out;

    cudaFuncSetAttribute(argmin_kernel,
                         cudaFuncAttributeMaxDynamicSharedMemorySize, SMEM_REQ);

    split_kernel<<<(NV * DD + KC * DD) / 4 / 256, 256>>>(ze, cb);
    norm_kernel<<<512, 256>>>(cb);
    argmin_kernel<<<NV / BM, 256, SMEM_REQ>>>(ze, cb, out);
    finalize_kernel<<<1, 256>>>(out);
}

// round 6
// speedup vs baseline: 4.9762x; 2.9149x over previous
#include <cuda_runtime.h>
#include <cuda_fp16.h>
#include <math.h>
#include <stdint.h>

// ---------------------------------------------------------------------------
// Problem constants
// ---------------------------------------------------------------------------
#define NV 16384   // encoded vectors
#define DD 256     // embedding dim
#define KC 4096    // codebook size

#define BM 128
#define BN 128
#define NTILES (KC / BN)     // 32

// SMEM tile images: 128 rows x 512 B (256 halves), 16B units xor-swizzled
#define TILE_BYTES 65536
#define SMEM_A  0
#define SMEM_B0 65536
#define SMEM_B1 131072
#define SMEM_BAR 196608
#define SMEM_REQ (196608 + 64)

// ---------------------------------------------------------------------------
// Scratch (no allocations allowed). Stored as swizzled 128-row tile images:
// half index = tile*32768 + row_in_tile*256 + ((c16 ^ (row&7)) * 8) + e
// ---------------------------------------------------------------------------
__device__ __half g_zehi16[NV * DD];
__device__ __half g_cbhi16[KC * DD];
__device__ float  g_cn2[KC];          // 0.5 * ||cb_k||^2
__device__ int    g_counts[KC];
__device__ float  g_partials[128];

// ---------------------------------------------------------------------------
// PTX helpers (sm_90-base features only; NO 'a'-gated instructions)
// ---------------------------------------------------------------------------
__device__ __forceinline__ uint32_t smem_u32(const void* p) {
    uint32_t a;
    asm("{ .reg .u64 t; cvta.to.shared.u64 t, %1; cvt.u32.u64 %0, t; }" : "=r"(a) : "l"(p));
    return a;
}

#define MBARRIER_INIT(addr, cnt) \
    asm volatile("mbarrier.init.shared.b64 [%0], %1;" :: "r"((uint32_t)(addr)), "r"((uint32_t)(cnt)) : "memory")
#define MBARRIER_EXPECT_TX(addr, bytes) \
    asm volatile("mbarrier.arrive.expect_tx.shared.b64 _, [%0], %1;" \
                 :: "r"((uint32_t)(addr)), "r"((uint32_t)(bytes)) : "memory")

#define MBARRIER_WAIT_PARITY(mbar_smem_addr, phase_parity) do { \
    uint32_t _mbar = (uint32_t)(mbar_smem_addr); \
    uint32_t _parity = (uint32_t)(phase_parity); \
    uint32_t _done; \
    asm volatile( \
        "{\n\t" \
        ".reg .pred p;\n\t" \
        "mbarrier.try_wait.parity.acquire.cta.shared::cta.b64 p, [%1], %2;\n\t" \
        "selp.b32 %0, 1, 0, p;\n\t" \
        "}" \
        : "=r"(_done) : "r"(_mbar), "r"(_parity) : "memory"); \
    if (!_done) { \
        asm volatile( \
            "{\n\t" \
            ".reg .pred P1;\n\t" \
            "WAIT_LOOP_%=:\n\t" \
            "mbarrier.try_wait.parity.acquire.cta.shared::cta.b64 P1, [%0], %1, 0x989680;\n\t" \
            "@P1 bra.uni WAIT_DONE_%=;\n\t" \
            "bra.uni WAIT_LOOP_%=;\n\t" \
            "WAIT_DONE_%=:\n\t" \
            "}" \
            :: "r"(_mbar), "r"(_parity) : "memory"); \
    } \
} while (0)

__device__ __forceinline__ void bulk_ld(uint32_t dst, const void* src, uint32_t bytes, uint32_t mbar) {
    asm volatile(
        "cp.async.bulk.shared::cluster.global.mbarrier::complete_tx::bytes [%0], [%1], %2, [%3];"
        :: "r"(dst), "l"(src), "r"(bytes), "r"(mbar) : "memory");
}

#define LDMX4(r, addr) \
    asm volatile("ldmatrix.sync.aligned.m8n8.x4.shared.b16 {%0,%1,%2,%3}, [%4];" \
        : "=r"((r)[0]), "=r"((r)[1]), "=r"((r)[2]), "=r"((r)[3]) : "r"(addr))

#define MMA16816(d, a, b0v, b1v) \
    asm volatile("mma.sync.aligned.m16n8k16.row.col.f32.f16.f16.f32 " \
        "{%0,%1,%2,%3}, {%4,%5,%6,%7}, {%8,%9}, {%0,%1,%2,%3};" \
        : "+f"((d)[0]), "+f"((d)[1]), "+f"((d)[2]), "+f"((d)[3]) \
        : "r"((a)[0]), "r"((a)[1]), "r"((a)[2]), "r"((a)[3]), "r"(b0v), "r"(b1v))

// ---------------------------------------------------------------------------
// Kernel 1: fp16 convert into swizzled tile images (one 16B unit per thread)
// ---------------------------------------------------------------------------
__global__ void split_kernel(const float* __restrict__ ze, const float* __restrict__ cb) {
    const int u = blockIdx.x * 256 + threadIdx.x;   // grid 2560 x 256 exact
    const int ZU = NV * 32;                         // 16B units in ze
    const float4* src; __half* dst; int v;
    if (u < ZU) { src = (const float4*)ze; dst = g_zehi16; v = u; }
    else        { src = (const float4*)cb; dst = g_cbhi16; v = u - ZU; }
    const int row = v >> 5, c16 = v & 31;
    const int tile = row >> 7, rin = row & 127;
    float4 f0 = src[v * 2], f1 = src[v * 2 + 1];
    __half2 h0 = __floats2half2_rn(f0.x, f0.y);
    __half2 h1 = __floats2half2_rn(f0.z, f0.w);
    __half2 h2 = __floats2half2_rn(f1.x, f1.y);
    __half2 h3 = __floats2half2_rn(f1.z, f1.w);
    uint4 w;
    w.x = *(uint32_t*)&h0; w.y = *(uint32_t*)&h1;
    w.z = *(uint32_t*)&h2; w.w = *(uint32_t*)&h3;
    const size_t d = (size_t)tile * 32768 + rin * 256 + ((c16 ^ (rin & 7)) * 8);
    *(uint4*)(dst + d) = w;
}

// ---------------------------------------------------------------------------
// Kernel 2: codebook half-norms (warp per code) + zero counts
// ---------------------------------------------------------------------------
__global__ void norm_kernel(const float* __restrict__ cb) {
    int gid  = blockIdx.x * 256 + threadIdx.x;   // 512 x 256 = 4096 warps
    int code = gid >> 5;
    int lane = gid & 31;
    const float* row = cb + (size_t)code * DD;
    float s = 0.f;
#pragma unroll
    for (int i = 0; i < DD; i += 32) { float v = row[i + lane]; s += v * v; }
#pragma unroll
    for (int off = 16; off; off >>= 1) s += __shfl_down_sync(0xffffffffu, s, off);
    if (lane == 0) g_cn2[code] = 0.5f * s;
    if (gid < KC) g_counts[gid] = 0;
}

// ---------------------------------------------------------------------------
// Kernel 3: single-pass fp16 mma GEMM + per-row approx top-2 + exact refine
//   A tile (128 rows x D) resident in SMEM; B tiles (128 codes x D) streamed
//   via cp.async.bulk + mbarrier, double buffered. 8 warps: 2(m) x 4(n),
//   warp tile 64x32. score = dot - 0.5*||c||^2 (maximize).
//   Refine: exact fp32 distance for each row's top-2 candidates.
// ---------------------------------------------------------------------------
__global__ void __launch_bounds__(256, 1) argmin_kernel(
    const float* __restrict__ ze, const float* __restrict__ cb,
    float* __restrict__ out)
{
    extern __shared__ char smraw[];
    const uint32_t smb = smem_u32(smraw);
    const uint32_t barA = smb + SMEM_BAR;
    const uint32_t barB0 = smb + SMEM_BAR + 8;
    const uint32_t barB1 = smb + SMEM_BAR + 16;

    const int tid    = threadIdx.x;
    const int lane   = tid & 31;
    const int wid    = tid >> 5;
    const int warp_m = wid & 1;
    const int warp_n = wid >> 1;
    const int r0     = blockIdx.x * BM;

    if (tid == 0) {
        MBARRIER_INIT(barA, 1);
        MBARRIER_INIT(barB0, 1);
        MBARRIER_INIT(barB1, 1);
    }
    __syncthreads();

    if (tid == 0) {
        MBARRIER_EXPECT_TX(barA, TILE_BYTES);
        bulk_ld(smb + SMEM_A, g_zehi16 + (size_t)blockIdx.x * 32768, TILE_BYTES, barA);
        MBARRIER_EXPECT_TX(barB0, TILE_BYTES);
        bulk_ld(smb + SMEM_B0, g_cbhi16, TILE_BYTES, barB0);
    }

    // ---- per-thread fragment addressing (swizzled image layout) ----
    const int x7   = lane & 7;
    const int a_hi = lane >> 4;                                   // c16 +0/+1
    const int b_hi = (lane >> 3) & 1;
    const uint32_t a_ro = (uint32_t)(warp_m * 64 + (lane & 15)) * 512;
    const uint32_t b_ro = (uint32_t)(warp_n * 32 + ((lane >> 4) << 3) + (lane & 7)) * 512;

    float acc[16][4];
#pragma unroll
    for (int i = 0; i < 16; i++)
#pragma unroll
        for (int j = 0; j < 4; j++) acc[i][j] = 0.f;

    float b1v[8], b2v[8];
    int   b1i[8], b2i[8];
#pragma unroll
    for (int i = 0; i < 8; i++) { b1v[i] = -3.4e38f; b2v[i] = -3.4e38f; b1i[i] = 0; b2i[i] = 1; }

    MBARRIER_WAIT_PARITY(barA, 0);
    int phB[2] = {0, 0};

    for (int nt = 0; nt < NTILES; nt++) {
        const int b = nt & 1;
        if (nt + 1 < NTILES && tid == 0) {
            // buffer b^1 last consumed in tile nt-1; freed by trailing sync
            const uint32_t bar = (b ? barB0 : barB1);
            MBARRIER_EXPECT_TX(bar, TILE_BYTES);
            bulk_ld(smb + (b ? SMEM_B0 : SMEM_B1), g_cbhi16 + (size_t)(nt + 1) * 32768,
                    TILE_BYTES, bar);
        }
        MBARRIER_WAIT_PARITY((b ? barB1 : barB0), phB[b]);
        phB[b] ^= 1;

        const uint32_t aBase = smb + SMEM_A + a_ro;
        const uint32_t bBase = smb + (b ? SMEM_B1 : SMEM_B0) + b_ro;

#pragma unroll
        for (int ks = 0; ks < 16; ks++) {          // dk*2+kk, 16 k16-steps
            const int c2 = ks * 2;
            uint32_t Af[4][4], Bf[2][4];
            const uint32_t ca = (uint32_t)(((c2 + a_hi) ^ x7) << 4);
            const uint32_t cbo = (uint32_t)(((c2 + b_hi) ^ x7) << 4);
#pragma unroll
            for (int mt = 0; mt < 4; mt++) LDMX4(Af[mt], aBase + mt * (16 * 512) + ca);
#pragma unroll
            for (int p = 0; p < 2; p++)    LDMX4(Bf[p], bBase + p * (16 * 512) + cbo);
#pragma unroll
            for (int mt = 0; mt < 4; mt++)
#pragma unroll
                for (int ntt = 0; ntt < 4; ntt++)
                    MMA16816(acc[mt * 4 + ntt], Af[mt],
                             Bf[ntt >> 1][(ntt & 1) * 2], Bf[ntt >> 1][(ntt & 1) * 2 + 1]);
        }

        // ---- fold -0.5||c||^2, update per-thread top-2, reset accs ----
        const int cbase = nt * BN + warp_n * 32 + (lane & 3) * 2;
#pragma unroll
        for (int j = 0; j < 4; j++) {
            const int   c0  = cbase + j * 8;
            const float cn0 = __ldg(g_cn2 + c0);
            const float cn1 = __ldg(g_cn2 + c0 + 1);
#pragma unroll
            for (int mt = 0; mt < 4; mt++) {
                float* a = acc[mt * 4 + j];
                const int rs0 = mt * 2, rs1 = mt * 2 + 1;
                const float v0 = a[0] - cn0, v1 = a[1] - cn1;
                const float v2 = a[2] - cn0, v3 = a[3] - cn1;
                if (v0 > b1v[rs0]) { b2v[rs0] = b1v[rs0]; b2i[rs0] = b1i[rs0]; b1v[rs0] = v0; b1i[rs0] = c0; }
                else if (v0 > b2v[rs0]) { b2v[rs0] = v0; b2i[rs0] = c0; }
                if (v1 > b1v[rs0]) { b2v[rs0] = b1v[rs0]; b2i[rs0] = b1i[rs0]; b1v[rs0] = v1; b1i[rs0] = c0 + 1; }
                else if (v1 > b2v[rs0]) { b2v[rs0] = v1; b2i[rs0] = c0 + 1; }
                if (v2 > b1v[rs1]) { b2v[rs1] = b1v[rs1]; b2i[rs1] = b1i[rs1]; b1v[rs1] = v2; b1i[rs1] = c0; }
                else if (v2 > b2v[rs1]) { b2v[rs1] = v2; b2i[rs1] = c0; }
                if (v3 > b1v[rs1]) { b2v[rs1] = b1v[rs1]; b2i[rs1] = b1i[rs1]; b1v[rs1] = v3; b1i[rs1] = c0 + 1; }
                else if (v3 > b2v[rs1]) { b2v[rs1] = v3; b2i[rs1] = c0 + 1; }
                a[0] = a[1] = a[2] = a[3] = 0.f;
            }
        }
        __syncthreads();   // all threads done reading buffer b before refill
    }

    // ---- cross-thread top-2 merge (quad via shuffle, warps via smem) ----
    float* sB1 = (float*)smraw;                  // [128][4]
    int*   sI1 = (int*)(smraw + 2048);
    float* sB2 = (float*)(smraw + 4096);
    int*   sI2 = (int*)(smraw + 6144);
    const int g = lane >> 2;

#pragma unroll
    for (int rs = 0; rs < 8; rs++) {
        float v1 = b1v[rs], v2 = b2v[rs];
        int   i1 = b1i[rs], i2 = b2i[rs];
#pragma unroll
        for (int off = 1; off <= 2; off <<= 1) {
            const float o1 = __shfl_xor_sync(0xffffffffu, v1, off);
            const int   oi1 = __shfl_xor_sync(0xffffffffu, i1, off);
            const float o2 = __shfl_xor_sync(0xffffffffu, v2, off);
            const int   oi2 = __shfl_xor_sync(0xffffffffu, i2, off);
            if (o1 > v1) {
                const float n2 = (v1 > o2) ? v1 : o2;
                const int   n2i = (v1 > o2) ? i1 : oi2;
                v2 = n2; i2 = n2i; v1 = o1; i1 = oi1;
            } else if (o1 > v2) { v2 = o1; i2 = oi1; }
        }
        if ((lane & 3) == 0) {
            const int rl = warp_m * 64 + (rs >> 1) * 16 + (rs & 1) * 8 + g;
            sB1[rl * 4 + warp_n] = v1; sI1[rl * 4 + warp_n] = i1;
            sB2[rl * 4 + warp_n] = v2; sI2[rl * 4 + warp_n] = i2;
        }
    }
    __syncthreads();

    float s = 0.f;
    if (tid < 128) {
        float v1 = sB1[tid * 4], v2 = sB2[tid * 4];
        int   i1 = sI1[tid * 4], i2 = sI2[tid * 4];
#pragma unroll
        for (int w = 1; w < 4; w++) {
            const float o1 = sB1[tid * 4 + w], o2 = sB2[tid * 4 + w];
            const int   oi1 = sI1[tid * 4 + w], oi2 = sI2[tid * 4 + w];
            if (o1 > v1) {
                const float n2 = (v1 > o2) ? v1 : o2;
                const int   n2i = (v1 > o2) ? i1 : oi2;
                v2 = n2; i2 = n2i; v1 = o1; i1 = oi1;
            } else if (o1 > v2) { v2 = o1; i2 = oi1; }
        }

        // ---- exact fp32 refine of the two candidates ----
        const int row = r0 + tid;
        const float4* zr = (const float4*)(ze + (size_t)row * DD);
        const float4* c1r = (const float4*)(cb + (size_t)i1 * DD);
        const float4* c2r = (const float4*)(cb + (size_t)i2 * DD);
        float d1 = 0.f, d2 = 0.f;
#pragma unroll 4
        for (int j = 0; j < DD / 4; j++) {
            const float4 z = zr[j], a = c1r[j], bq = c2r[j];
            float t;
            t = z.x - a.x; d1 += t * t;  t = z.y - a.y; d1 += t * t;
            t = z.z - a.z; d1 += t * t;  t = z.w - a.w; d1 += t * t;
            t = z.x - bq.x; d2 += t * t; t = z.y - bq.y; d2 += t * t;
            t = z.z - bq.z; d2 += t * t; t = z.w - bq.w; d2 += t * t;
        }
        int ix; float dl;
        if (d2 < d1 || (d2 == d1 && i2 < i1)) { ix = i2; dl = d2; }
        else                                  { ix = i1; dl = d1; }

        out[row] = (float)ix;
        atomicAdd(&g_counts[ix], 1);
        s = dl;   // sum of squared error for this row == loss partial

        const float4* cr = (const float4*)(cb + (size_t)ix * DD);
        float4* orow = (float4*)(out + NV + (size_t)row * DD);
#pragma unroll 4
        for (int j = 0; j < DD / 4; j++) orow[j] = cr[j];
    }
    __syncthreads();
    float* red = (float*)(smraw + 8192);
    red[tid] = s;
    __syncthreads();
    for (int off = 128; off; off >>= 1) {
        if (tid < off) red[tid] += red[tid + off];
        __syncthreads();
    }
    if (tid == 0) g_partials[blockIdx.x] = red[0];
}

// ---------------------------------------------------------------------------
// Kernel 4: losses + perplexity
// ---------------------------------------------------------------------------
__global__ void finalize_kernel(float* __restrict__ out) {
    __shared__ float red[256];
    const int t = threadIdx.x;

    red[t] = (t < 128) ? g_partials[t] : 0.f;
    __syncthreads();
    for (int off = 128; off; off >>= 1) {
        if (t < off) red[t] += red[t + off];
        __syncthreads();
    }
    if (t == 0) {
        float loss = red[0] / (float)((size_t)NV * DD);
        out[(size_t)NV + (size_t)NV * DD + 0] = loss;
        out[(size_t)NV + (size_t)NV * DD + 1] = loss;
    }
    __syncthreads();

    float e = 0.f;
    for (int k = t; k < KC; k += 256) {
        float p = (float)g_counts[k] * 0.1f;
        e += p * logf(p + 1e-10f);
    }
    red[t] = e;
    __syncthreads();
    for (int off = 128; off; off >>= 1) {
        if (t < off) red[t] += red[t + off];
        __syncthreads();
    }
    if (t == 0) out[(size_t)NV + (size_t)NV * DD + 2] = expf(-red[0]);
}

// ---------------------------------------------------------------------------
extern "C" void kernel_launch(void* const* d_in, const int* in_sizes, int n_in,
                              void* d_out, int out_size)
{
    const float* ze = (const float*)d_in[0];
    const float* cb = (const float*)d_in[1];
    float* out = (float*)d_out;

    cudaFuncSetAttribute(argmin_kernel,
                         cudaFuncAttributeMaxDynamicSharedMemorySize, SMEM_REQ);

    split_kernel<<<(NV + KC) * 32 / 256, 256>>>(ze, cb);
    norm_kernel<<<512, 256>>>(cb);
    argmin_kernel<<<NV / BM, 256, SMEM_REQ>>>(ze, cb, out);
    finalize_kernel<<<1, 256>>>(out);
}